// round 15
// baseline (speedup 1.0000x reference)
#include <cuda_runtime.h>
#include <math.h>

#define N_PTS   8192
#define GDIM    12
#define NCELLS  1728                          // 12^3
#define CELL_H  0.025f
#define INV_H   40.0f
#define H2      6.25e-4f                      // 0.025^2
#define THR2    4.0e-4f                       // 0.02^2
#define BIGF    1.0e30f
#define CAP     32                            // bucket capacity (mean 4.7/cell)
#define SMEM_CAND 384                         // region candidate capacity (mean ~128)
#define NTHR    64

// ---------------- device scratch (no allocations allowed) ----------------
__device__ int    g_cnt[NCELLS];              // zero-init; main_k last block restores
__device__ int    g_done;                     // zero-init; main_k last block restores
__device__ float4 g_bpos[NCELLS * CAP];       // bucketed (x,y,z,|p|^2)
__device__ float4 g_bquat[NCELLS * CAP];
__device__ int    g_borig[NCELLS * CAP];
__device__ float  g_flat[N_PTS];
__device__ float4 g_part[NCELLS];             // per-block partials (F,D,A,C)

// ---------------- helpers ----------------
__device__ __forceinline__ void insert9(float (&t)[9], float d) {
    if (d < t[8]) {
        t[8] = d;
        #pragma unroll
        for (int k = 8; k > 0; --k) {
            float lo = fminf(t[k - 1], t[k]);
            float hi = fmaxf(t[k - 1], t[k]);
            t[k - 1] = lo;
            t[k]     = hi;
        }
    }
}

// Full-warp collective extraction: 9 smallest across 32 sorted per-lane lists.
// Returns mean excluding global min (self); reports 9th-smallest d2. Destroys t.
__device__ __forceinline__ float knn_extract_warp(float (&t)[9], int lane, float* ninth) {
    float sum = 0.0f, mn = 0.0f, last = 0.0f;
    #pragma unroll
    for (int r = 0; r < 9; ++r) {
        float cand = t[0];
        float v = cand;
        #pragma unroll
        for (int off = 16; off > 0; off >>= 1)
            v = fminf(v, __shfl_xor_sync(0xffffffffu, v, off));
        unsigned m = __ballot_sync(0xffffffffu, cand == v);
        if (lane == (__ffs(m) - 1)) {
            #pragma unroll
            for (int k = 0; k < 8; ++k) t[k] = t[k + 1];
            t[8] = BIGF;
        }
        float d = sqrtf(fmaxf(v, 0.0f) + 1e-12f);
        if (r == 0) mn = d;
        if (r == 8) last = v;
        sum += d;
    }
    *ninth = last;
    return (sum - mn) * 0.125f;
}

// ---------------- scatter: bucket points + per-point flatness ----------------
__global__ __launch_bounds__(128)
void scatter_k(const float* __restrict__ pos,
               const float4* __restrict__ rot,
               const float* __restrict__ scales) {
    int i = blockIdx.x * 128 + threadIdx.x;

    float x = pos[3 * i + 0], y = pos[3 * i + 1], z = pos[3 * i + 2];
    int cx = min(GDIM - 1, max(0, (int)(x * INV_H)));
    int cy = min(GDIM - 1, max(0, (int)(y * INV_H)));
    int cz = min(GDIM - 1, max(0, (int)(z * INV_H)));
    int cid = (cz * GDIM + cy) * GDIM + cx;

    int slot = atomicAdd(&g_cnt[cid], 1);
    if (slot < CAP) {
        int dst = cid * CAP + slot;
        g_bpos[dst]  = make_float4(x, y, z, fmaf(x, x, fmaf(y, y, z * z)));
        g_bquat[dst] = rot[i];
        g_borig[dst] = i;
    }

    float a = expf(scales[3 * i + 0]);
    float b = expf(scales[3 * i + 1]);
    float c = expf(scales[3 * i + 2]);
    float tt;
    if (a > b) { tt = a; a = b; b = tt; }
    if (b > c) { tt = b; b = c; c = tt; }
    if (a > b) { tt = a; a = b; b = tt; }
    g_flat[i] = logf(c / (a + 1e-8f) + 1e-8f) + 0.1f / (fabsf(c - b) + 0.001f);
}

// ---------------- main: block per cell, oct per row, fused final ----------------
__global__ __launch_bounds__(NTHR)
void main_k(const float* __restrict__ opacity, float* __restrict__ out) {
    __shared__ float4 s_p[SMEM_CAND];
    __shared__ float4 s_q[SMEM_CAND];
    __shared__ int    s_id[SMEM_CAND];
    __shared__ int    s_off[28];
    __shared__ int    s_base[27];
    __shared__ float  s_w[2][4];
    __shared__ int    s_last;

    const int cell = blockIdx.x;
    const int tid  = threadIdx.x;
    const int lane = tid & 31;
    const int warp = tid >> 5;

    const int cx = cell % GDIM;
    const int cy = (cell / GDIM) % GDIM;
    const int cz = cell / (GDIM * GDIM);
    const int x0 = max(cx - 1, 0), x1 = min(cx + 1, GDIM - 1);
    const int y0 = max(cy - 1, 0), y1 = min(cy + 1, GDIM - 1);
    const int z0 = max(cz - 1, 0), z1 = min(cz + 1, GDIM - 1);
    const int nx = x1 - x0 + 1, ny = y1 - y0 + 1, nz = z1 - z0 + 1;
    const int RC = nx * ny * nz;              // <= 27

    // warp 0: parallel counts + inclusive scan -> prefix offsets
    if (tid < 32) {
        int cnt2 = 0;
        if (tid < RC) {
            int lx = tid % nx, rem = tid / nx;
            int cid = ((z0 + rem / ny) * GDIM + (y0 + rem % ny)) * GDIM + (x0 + lx);
            s_base[tid] = cid * CAP;
            cnt2 = min(g_cnt[cid], CAP);
        }
        int v = cnt2;
        #pragma unroll
        for (int o = 1; o < 32; o <<= 1) {
            int u = __shfl_up_sync(0xffffffffu, v, o);
            if (lane >= o) v += u;
        }
        if (tid < 27) s_off[tid + 1] = v;
        if (tid == 0) s_off[0] = 0;
    }
    __syncthreads();

    const int total = s_off[RC];
    const bool oversize = (total > SMEM_CAND);

    if (!oversize) {
        for (int idx = tid; idx < total; idx += NTHR) {
            int lo = 0, hi = RC - 1;
            #pragma unroll
            for (int s = 0; s < 5; ++s) {
                int mid = (lo + hi + 1) >> 1;
                if (s_off[mid] <= idx) lo = mid; else hi = mid - 1;
            }
            int src = s_base[lo] + (idx - s_off[lo]);
            s_p[idx]  = g_bpos[src];
            s_q[idx]  = g_bquat[src];
            s_id[idx] = g_borig[src];
        }
    }
    __syncthreads();

    const int hc = (cx - x0) + nx * ((cy - y0) + ny * (cz - z0));
    const int ho = s_off[hc];
    const int myCnt = s_off[hc + 1] - ho;
    const int passes = (myCnt + 7) >> 3;      // uniform across block

    float Fp = 0.0f, Dp = 0.0f, Ap = 0.0f, Cp = 0.0f;

    for (int pass = 0; pass < passes; ++pass) {
        const int q   = (tid >> 3) + (pass << 3);   // row within home cell
        const int sub = tid & 7;                    // oct sub-thread
        const bool active = (q < myCnt);
        const int qs = active ? q : 0;
        const int myIdx = ho + qs;
        const int mySrc = cell * CAP + qs;

        float4 P, Q;
        int myid;
        if (!oversize) { P = s_p[myIdx]; Q = s_q[myIdx]; myid = s_id[myIdx]; }
        else           { P = g_bpos[mySrc]; Q = g_bquat[mySrc]; myid = g_borig[mySrc]; }

        float t[9];
        #pragma unroll
        for (int k = 0; k < 9; ++k) t[k] = H2;   // sentinel: 9th >= H2 => fallback
        float asum = 0.0f, acnt = 0.0f;

        if (!oversize) {
            for (int j = sub; j < total; j += 8) {
                float4 p = s_p[j];
                float dot = fmaf(P.x, p.x, fmaf(P.y, p.y, P.z * p.z));
                float d2  = fmaf(-2.0f, dot, P.w + p.w);
                insert9(t, d2);
                if (d2 < THR2 && j != myIdx) {       // alignment exact: 0.02 < h
                    float4 qq = s_q[j];
                    float qd = fmaf(Q.x, qq.x, fmaf(Q.y, qq.y, fmaf(Q.z, qq.z, Q.w * qq.w)));
                    asum += 1.0f - fabsf(qd);
                    acnt += 1.0f;
                }
            }
        } else {
            for (int c = 0; c < RC; ++c) {
                int cnt2 = s_off[c + 1] - s_off[c];
                int b2 = s_base[c];
                for (int j = sub; j < cnt2; j += 8) {
                    int slot = b2 + j;
                    float4 p = g_bpos[slot];
                    float dot = fmaf(P.x, p.x, fmaf(P.y, p.y, P.z * p.z));
                    float d2  = fmaf(-2.0f, dot, P.w + p.w);
                    insert9(t, d2);
                    if (d2 < THR2 && slot != mySrc) {
                        float4 qq = g_bquat[slot];
                        float qd = fmaf(Q.x, qq.x, fmaf(Q.y, qq.y, fmaf(Q.z, qq.z, Q.w * qq.w)));
                        asum += 1.0f - fabsf(qd);
                        acnt += 1.0f;
                    }
                }
            }
        }

        // oct-reduce alignment partials
        asum += __shfl_xor_sync(0xffffffffu, asum, 1);
        asum += __shfl_xor_sync(0xffffffffu, asum, 2);
        asum += __shfl_xor_sync(0xffffffffu, asum, 4);
        acnt += __shfl_xor_sync(0xffffffffu, acnt, 1);
        acnt += __shfl_xor_sync(0xffffffffu, acnt, 2);
        acnt += __shfl_xor_sync(0xffffffffu, acnt, 4);

        // oct-merge: 9 smallest of 8 sorted lists; drop global min (self)
        float sum = 0.0f, mn = 0.0f, last = 0.0f;
        #pragma unroll
        for (int r = 0; r < 9; ++r) {
            float cand = t[0];
            float v = fminf(cand, __shfl_xor_sync(0xffffffffu, cand, 1));
            v = fminf(v, __shfl_xor_sync(0xffffffffu, v, 2));
            v = fminf(v, __shfl_xor_sync(0xffffffffu, v, 4));
            unsigned blt = __ballot_sync(0xffffffffu, cand == v);
            int ob = lane & ~7;
            int leader = ob + __ffs((blt >> ob) & 0xffu) - 1;
            if (lane == leader) {
                #pragma unroll
                for (int k = 0; k < 8; ++k) t[k] = t[k + 1];
                t[8] = BIGF;
            }
            float d = sqrtf(fmaxf(v, 0.0f) + 1e-12f);
            if (r == 0) mn = d;
            sum += d;
            if (r == 8) last = v;
        }
        float knn = (sum - mn) * 0.125f;
        const bool ok = (last < H2);

        // stage-2 fallback: warp-cooperative radius-doubling box rescan (exact)
        unsigned bad = __ballot_sync(0xffffffffu, active && !ok && (sub == 0));
        while (bad) {
            int src = __ffs(bad) - 1;
            bad &= bad - 1;
            float4 Pb;
            Pb.x = __shfl_sync(0xffffffffu, P.x, src);
            Pb.y = __shfl_sync(0xffffffffu, P.y, src);
            Pb.z = __shfl_sync(0xffffffffu, P.z, src);
            Pb.w = __shfl_sync(0xffffffffu, P.w, src);
            float kv = 0.0f;
            int radius = 2;
            for (;;) {
                float sent  = CELL_H * (float)radius;
                float sent2 = sent * sent;
                int ex0 = max(cx - radius, 0), ex1 = min(cx + radius, GDIM - 1);
                int ey0 = max(cy - radius, 0), ey1 = min(cy + radius, GDIM - 1);
                int ez0 = max(cz - radius, 0), ez1 = min(cz + radius, GDIM - 1);
                float tb[9];
                #pragma unroll
                for (int k = 0; k < 9; ++k) tb[k] = sent2;
                for (int z = ez0; z <= ez1; ++z)
                    for (int y = ey0; y <= ey1; ++y)
                        for (int x = ex0; x <= ex1; ++x) {
                            int c2 = (z * GDIM + y) * GDIM + x;
                            int cnt2 = min(g_cnt[c2], CAP);
                            int b2 = c2 * CAP;
                            for (int j = lane; j < cnt2; j += 32) {
                                float4 p = g_bpos[b2 + j];
                                float dot = fmaf(Pb.x, p.x, fmaf(Pb.y, p.y, Pb.z * p.z));
                                float d2  = fmaf(-2.0f, dot, Pb.w + p.w);
                                insert9(tb, d2);
                            }
                        }
                float ninth;
                kv = knn_extract_warp(tb, lane, &ninth);
                bool fullbox = (ex0 == 0) && (ex1 == GDIM - 1) && (ey0 == 0) &&
                               (ey1 == GDIM - 1) && (ez0 == 0) && (ez1 == GDIM - 1);
                if (ninth < sent2 || fullbox) break;
                radius <<= 1;
            }
            if (lane == src) knn = kv;
        }

        if (active && sub == 0) {
            Ap += asum;
            Cp += acnt;
            Dp += fabsf(knn - 0.01f) * opacity[myid];
            Fp += g_flat[myid];
        }
    }

    // ---------- block reduce + last-block-done final ----------
    #pragma unroll
    for (int o = 16; o > 0; o >>= 1) {
        Fp += __shfl_down_sync(0xffffffffu, Fp, o);
        Dp += __shfl_down_sync(0xffffffffu, Dp, o);
        Ap += __shfl_down_sync(0xffffffffu, Ap, o);
        Cp += __shfl_down_sync(0xffffffffu, Cp, o);
    }
    if (lane == 0) { s_w[warp][0] = Fp; s_w[warp][1] = Dp; s_w[warp][2] = Ap; s_w[warp][3] = Cp; }
    __syncthreads();
    if (tid == 0) {
        float4 bp;
        bp.x = s_w[0][0] + s_w[1][0];
        bp.y = s_w[0][1] + s_w[1][1];
        bp.z = s_w[0][2] + s_w[1][2];
        bp.w = s_w[0][3] + s_w[1][3];
        g_part[cell] = bp;
        __threadfence();
        int old = atomicAdd(&g_done, 1);
        s_last = (old == NCELLS - 1) ? 1 : 0;
    }
    __syncthreads();

    if (s_last) {
        float F = 0.0f, D = 0.0f, A = 0.0f, C = 0.0f;
        #pragma unroll
        for (int k = 0; k < NCELLS / NTHR; ++k) {
            float4 v = __ldcg(&g_part[tid + k * NTHR]);
            F += v.x; D += v.y; A += v.z; C += v.w;
        }
        #pragma unroll
        for (int o = 16; o > 0; o >>= 1) {
            F += __shfl_down_sync(0xffffffffu, F, o);
            D += __shfl_down_sync(0xffffffffu, D, o);
            A += __shfl_down_sync(0xffffffffu, A, o);
            C += __shfl_down_sync(0xffffffffu, C, o);
        }
        if (lane == 0) { s_w[warp][0] = F; s_w[warp][1] = D; s_w[warp][2] = A; s_w[warp][3] = C; }
        __syncthreads();
        if (tid == 0) {
            F = s_w[0][0] + s_w[1][0];
            D = s_w[0][1] + s_w[1][1];
            A = s_w[0][2] + s_w[1][2];
            C = s_w[0][3] + s_w[1][3];
            float flatness_loss  = -(F / (float)N_PTS);
            float alignment_loss = (C > 0.0f) ? (A / C) : 0.0f;
            float density_loss   = D / (float)N_PTS;
            out[0] = flatness_loss + 0.5f * alignment_loss + 0.2f * density_loss;
            g_done = 0;
        }
        // restore bucket counters for next graph replay
        #pragma unroll
        for (int k = 0; k < NCELLS / NTHR; ++k) g_cnt[tid + k * NTHR] = 0;
    }
}

// ---------------- launch ----------------
extern "C" void kernel_launch(void* const* d_in, const int* in_sizes, int n_in,
                              void* d_out, int out_size) {
    const float*  positions = (const float*)d_in[0];
    const float4* rotations = (const float4*)d_in[1];
    const float*  scales    = (const float*)d_in[2];
    const float*  opacity   = (const float*)d_in[3];
    float* out = (float*)d_out;

    scatter_k<<<N_PTS / 128, 128>>>(positions, rotations, scales);
    main_k<<<NCELLS, NTHR>>>(opacity, out);
}

// round 17
// speedup vs baseline: 3.0088x; 3.0088x over previous
#include <cuda_runtime.h>
#include <math.h>

#define N_PTS   8192
#define GDIM    8
#define NCELLS  512
#define INV_H   26.666666666666668f           // 1 / 0.0375
#define H2      0.00140625f                   // 0.0375^2
#define THR2    4.0e-4f                       // 0.02^2
#define BIGF    1.0e30f
#define CAP     48                            // bucket capacity (mean 16/cell)
#define SMEM_CAND 640                         // region candidate capacity
#define NBLK    512
#define NTHR    128

// ---------------- device scratch (no allocations allowed) ----------------
__device__ int    g_cnt[NCELLS];              // zero-init; main_k last block restores
__device__ int    g_done;                     // zero-init; main_k last block restores
__device__ float4 g_bpos[NCELLS * CAP];       // bucketed (x,y,z,|p|^2)
__device__ float4 g_bquat[NCELLS * CAP];
__device__ int    g_borig[NCELLS * CAP];
__device__ float  g_flat[N_PTS];
__device__ float4 g_part[NBLK];               // per-block partials (F,D,A,C)

// ---------------- helpers ----------------
__device__ __forceinline__ void insert9(float (&t)[9], float d) {
    if (d < t[8]) {
        t[8] = d;
        #pragma unroll
        for (int k = 8; k > 0; --k) {
            float lo = fminf(t[k - 1], t[k]);
            float hi = fmaxf(t[k - 1], t[k]);
            t[k - 1] = lo;
            t[k]     = hi;
        }
    }
}

// Full-warp collective extraction (exact fallback path only).
__device__ __forceinline__ float knn_mean_warp(float (&t)[9], int lane) {
    float sum = 0.0f, mn = 0.0f;
    #pragma unroll
    for (int r = 0; r < 9; ++r) {
        float cand = t[0];
        float v = cand;
        #pragma unroll
        for (int off = 16; off > 0; off >>= 1)
            v = fminf(v, __shfl_xor_sync(0xffffffffu, v, off));
        unsigned m = __ballot_sync(0xffffffffu, cand == v);
        if (lane == (__ffs(m) - 1)) {
            #pragma unroll
            for (int k = 0; k < 8; ++k) t[k] = t[k + 1];
            t[8] = BIGF;
        }
        float d = sqrtf(fmaxf(v, 0.0f) + 1e-12f);
        if (r == 0) mn = d;
        sum += d;
    }
    return (sum - mn) * 0.125f;
}

// ---------------- scatter: bucket points + per-point flatness ----------------
__global__ __launch_bounds__(256)
void scatter_k(const float* __restrict__ pos,
               const float4* __restrict__ rot,
               const float* __restrict__ scales) {
    int i = blockIdx.x * 256 + threadIdx.x;

    float x = pos[3 * i + 0], y = pos[3 * i + 1], z = pos[3 * i + 2];
    int cx = min(GDIM - 1, max(0, (int)(x * INV_H)));
    int cy = min(GDIM - 1, max(0, (int)(y * INV_H)));
    int cz = min(GDIM - 1, max(0, (int)(z * INV_H)));
    int cid = (cz * GDIM + cy) * GDIM + cx;

    int slot = atomicAdd(&g_cnt[cid], 1);
    if (slot < CAP) {
        int dst = cid * CAP + slot;
        g_bpos[dst]  = make_float4(x, y, z, fmaf(x, x, fmaf(y, y, z * z)));
        g_bquat[dst] = rot[i];
        g_borig[dst] = i;
    }

    float a = expf(scales[3 * i + 0]);
    float b = expf(scales[3 * i + 1]);
    float c = expf(scales[3 * i + 2]);
    float tt;
    if (a > b) { tt = a; a = b; b = tt; }
    if (b > c) { tt = b; b = c; c = tt; }
    if (a > b) { tt = a; a = b; b = tt; }
    g_flat[i] = logf(c / (a + 1e-8f) + 1e-8f) + 0.1f / (fabsf(c - b) + 0.001f);
}

// ---------------- main: block per cell, oct per row, fused final ----------------
__global__ __launch_bounds__(NTHR)
void main_k(const float*  __restrict__ pos,
            const float*  __restrict__ opacity,
            float* __restrict__ out) {
    __shared__ float4 s_p[SMEM_CAND];
    __shared__ float4 s_q[SMEM_CAND];
    __shared__ int    s_id[SMEM_CAND];
    __shared__ int    s_off[28];
    __shared__ int    s_base[27];
    __shared__ float  s_w[4][4];
    __shared__ int    s_last;

    const int cell = blockIdx.x;
    const int tid  = threadIdx.x;
    const int lane = tid & 31;
    const int warp = tid >> 5;

    // ---------- region setup (warp 0) ----------
    const int cx = cell & 7, cy = (cell >> 3) & 7, cz = cell >> 6;
    const int x0 = max(cx - 1, 0), x1 = min(cx + 1, 7);
    const int y0 = max(cy - 1, 0), y1 = min(cy + 1, 7);
    const int z0 = max(cz - 1, 0), z1 = min(cz + 1, 7);
    const int nx = x1 - x0 + 1, ny = y1 - y0 + 1, nz = z1 - z0 + 1;
    const int RC = nx * ny * nz;              // <= 27

    if (tid < 32) {
        int cnt2 = 0;
        if (tid < RC) {
            int lx = tid % nx, rem = tid / nx;
            int cid = ((z0 + rem / ny) * GDIM + (y0 + rem % ny)) * GDIM + (x0 + lx);
            s_base[tid] = cid * CAP;
            cnt2 = min(g_cnt[cid], CAP);
        }
        int v = cnt2;
        #pragma unroll
        for (int o = 1; o < 32; o <<= 1) {
            int u = __shfl_up_sync(0xffffffffu, v, o);
            if (lane >= o) v += u;
        }
        if (tid < 27) s_off[tid + 1] = v;
        if (tid == 0) s_off[0] = 0;
    }
    __syncthreads();

    const int total = s_off[RC];
    const bool oversize = (total > SMEM_CAND);

    if (!oversize) {
        for (int idx = tid; idx < total; idx += NTHR) {
            int lo = 0, hi = RC - 1;
            #pragma unroll
            for (int s = 0; s < 5; ++s) {
                int mid = (lo + hi + 1) >> 1;
                if (s_off[mid] <= idx) lo = mid; else hi = mid - 1;
            }
            int src = s_base[lo] + (idx - s_off[lo]);
            s_p[idx]  = g_bpos[src];
            s_q[idx]  = g_bquat[src];
            s_id[idx] = g_borig[src];
        }
    }
    __syncthreads();

    const int hc = (cx - x0) + nx * ((cy - y0) + ny * (cz - z0));
    const int ho = s_off[hc];
    const int myCnt = s_off[hc + 1] - ho;
    const int passes = (myCnt + 15) >> 4;     // 16 rows per pass (oct per row)

    float Fp = 0.0f, Dp = 0.0f, Ap = 0.0f, Cp = 0.0f;

    for (int pass = 0; pass < passes; ++pass) {
        const int q   = (tid >> 3) + (pass << 4);   // row within home cell
        const int sub = tid & 7;                    // oct sub-thread
        const bool active = (q < myCnt);
        const int qs = active ? q : 0;
        const int myIdx = ho + qs;
        const int mySrc = cell * CAP + qs;

        float4 P, Q;
        int myid;
        if (!oversize) { P = s_p[myIdx]; Q = s_q[myIdx]; myid = s_id[myIdx]; }
        else           { P = g_bpos[mySrc]; Q = g_bquat[mySrc]; myid = g_borig[mySrc]; }

        float t[9];
        #pragma unroll
        for (int k = 0; k < 9; ++k) t[k] = H2;   // sentinel: 9th >= H2 => fallback
        float asum = 0.0f, acnt = 0.0f;

        if (!oversize) {
            for (int j = sub; j < total; j += 8) {
                float4 p = s_p[j];
                float dot = fmaf(P.x, p.x, fmaf(P.y, p.y, P.z * p.z));
                float d2  = fmaf(-2.0f, dot, P.w + p.w);
                insert9(t, d2);
                if (d2 < THR2 && j != myIdx) {       // alignment exact: 0.02 < h
                    float4 qq = s_q[j];
                    float qd = fmaf(Q.x, qq.x, fmaf(Q.y, qq.y, fmaf(Q.z, qq.z, Q.w * qq.w)));
                    asum += 1.0f - fabsf(qd);
                    acnt += 1.0f;
                }
            }
        } else {
            for (int c = 0; c < RC; ++c) {
                int cnt2 = s_off[c + 1] - s_off[c];
                int b2 = s_base[c];
                for (int j = sub; j < cnt2; j += 8) {
                    int slot = b2 + j;
                    float4 p = g_bpos[slot];
                    float dot = fmaf(P.x, p.x, fmaf(P.y, p.y, P.z * p.z));
                    float d2  = fmaf(-2.0f, dot, P.w + p.w);
                    insert9(t, d2);
                    if (d2 < THR2 && slot != mySrc) {
                        float4 qq = g_bquat[slot];
                        float qd = fmaf(Q.x, qq.x, fmaf(Q.y, qq.y, fmaf(Q.z, qq.z, Q.w * qq.w)));
                        asum += 1.0f - fabsf(qd);
                        acnt += 1.0f;
                    }
                }
            }
        }

        // oct-reduce alignment partials
        asum += __shfl_xor_sync(0xffffffffu, asum, 1);
        asum += __shfl_xor_sync(0xffffffffu, asum, 2);
        asum += __shfl_xor_sync(0xffffffffu, asum, 4);
        acnt += __shfl_xor_sync(0xffffffffu, acnt, 1);
        acnt += __shfl_xor_sync(0xffffffffu, acnt, 2);
        acnt += __shfl_xor_sync(0xffffffffu, acnt, 4);

        // oct-merge: 9 smallest of 8 sorted lists; drop global min (self)
        float sum = 0.0f, mn = 0.0f, last = 0.0f;
        #pragma unroll
        for (int r = 0; r < 9; ++r) {
            float cand = t[0];
            float v = fminf(cand, __shfl_xor_sync(0xffffffffu, cand, 1));
            v = fminf(v, __shfl_xor_sync(0xffffffffu, v, 2));
            v = fminf(v, __shfl_xor_sync(0xffffffffu, v, 4));
            unsigned blt = __ballot_sync(0xffffffffu, cand == v);
            int ob = lane & ~7;
            int leader = ob + __ffs((blt >> ob) & 0xffu) - 1;
            if (lane == leader) {
                #pragma unroll
                for (int k = 0; k < 8; ++k) t[k] = t[k + 1];
                t[8] = BIGF;
            }
            float d = sqrtf(fmaxf(v, 0.0f) + 1e-12f);
            if (r == 0) mn = d;
            sum += d;
            if (r == 8) last = v;
        }
        float knn = (sum - mn) * 0.125f;
        const bool ok = (last < H2);

        // rare exact fallback: warp-cooperative brute force over all points
        unsigned bad = __ballot_sync(0xffffffffu, active && !ok && (sub == 0));
        while (bad) {
            int src = __ffs(bad) - 1;
            bad &= bad - 1;
            float4 Pb;
            Pb.x = __shfl_sync(0xffffffffu, P.x, src);
            Pb.y = __shfl_sync(0xffffffffu, P.y, src);
            Pb.z = __shfl_sync(0xffffffffu, P.z, src);
            Pb.w = __shfl_sync(0xffffffffu, P.w, src);
            float tb[9];
            #pragma unroll
            for (int k = 0; k < 9; ++k) tb[k] = BIGF;
            for (int j = lane; j < N_PTS; j += 32) {
                float px = pos[3 * j + 0], py = pos[3 * j + 1], pz = pos[3 * j + 2];
                float sqj = fmaf(px, px, fmaf(py, py, pz * pz));
                float dot = fmaf(Pb.x, px, fmaf(Pb.y, py, Pb.z * pz));
                float d2  = fmaf(-2.0f, dot, Pb.w + sqj);
                insert9(tb, d2);
            }
            float kv = knn_mean_warp(tb, lane);   // warp-uniform
            if (lane == src) knn = kv;
        }

        if (active && sub == 0) {
            Ap += asum;
            Cp += acnt;
            Dp += fabsf(knn - 0.01f) * opacity[myid];
            Fp += g_flat[myid];
        }
    }

    // ---------- block reduce + last-block-done final ----------
    #pragma unroll
    for (int o = 16; o > 0; o >>= 1) {
        Fp += __shfl_down_sync(0xffffffffu, Fp, o);
        Dp += __shfl_down_sync(0xffffffffu, Dp, o);
        Ap += __shfl_down_sync(0xffffffffu, Ap, o);
        Cp += __shfl_down_sync(0xffffffffu, Cp, o);
    }
    if (lane == 0) { s_w[warp][0] = Fp; s_w[warp][1] = Dp; s_w[warp][2] = Ap; s_w[warp][3] = Cp; }
    __syncthreads();
    if (tid == 0) {
        float4 bp = make_float4(0.0f, 0.0f, 0.0f, 0.0f);
        #pragma unroll
        for (int w = 0; w < 4; ++w) {
            bp.x += s_w[w][0]; bp.y += s_w[w][1];
            bp.z += s_w[w][2]; bp.w += s_w[w][3];
        }
        g_part[cell] = bp;
        __threadfence();
        int old = atomicAdd(&g_done, 1);
        s_last = (old == NBLK - 1) ? 1 : 0;
    }
    __syncthreads();

    if (s_last) {
        float F = 0.0f, D = 0.0f, A = 0.0f, C = 0.0f;
        #pragma unroll
        for (int k = 0; k < NBLK / NTHR; ++k) {
            float4 v = __ldcg(&g_part[tid + k * NTHR]);
            F += v.x; D += v.y; A += v.z; C += v.w;
        }
        #pragma unroll
        for (int o = 16; o > 0; o >>= 1) {
            F += __shfl_down_sync(0xffffffffu, F, o);
            D += __shfl_down_sync(0xffffffffu, D, o);
            A += __shfl_down_sync(0xffffffffu, A, o);
            C += __shfl_down_sync(0xffffffffu, C, o);
        }
        if (lane == 0) { s_w[warp][0] = F; s_w[warp][1] = D; s_w[warp][2] = A; s_w[warp][3] = C; }
        __syncthreads();
        if (tid == 0) {
            F = 0.0f; D = 0.0f; A = 0.0f; C = 0.0f;
            #pragma unroll
            for (int w = 0; w < 4; ++w) {
                F += s_w[w][0]; D += s_w[w][1];
                A += s_w[w][2]; C += s_w[w][3];
            }
            float flatness_loss  = -(F / (float)N_PTS);
            float alignment_loss = (C > 0.0f) ? (A / C) : 0.0f;
            float density_loss   = D / (float)N_PTS;
            out[0] = flatness_loss + 0.5f * alignment_loss + 0.2f * density_loss;
            g_done = 0;
        }
        // restore bucket counters for next graph replay
        #pragma unroll
        for (int k = 0; k < NCELLS / NTHR; ++k) g_cnt[tid + k * NTHR] = 0;
    }
}

// ---------------- launch ----------------
extern "C" void kernel_launch(void* const* d_in, const int* in_sizes, int n_in,
                              void* d_out, int out_size) {
    const float*  positions = (const float*)d_in[0];
    const float4* rotations = (const float4*)d_in[1];
    const float*  scales    = (const float*)d_in[2];
    const float*  opacity   = (const float*)d_in[3];
    float* out = (float*)d_out;

    scatter_k<<<N_PTS / 256, 256>>>(positions, rotations, scales);
    main_k<<<NBLK, NTHR>>>(positions, opacity, out);
}